// round 6
// baseline (speedup 1.0000x reference)
#include <cuda_runtime.h>
#include <math.h>

#define BATCH_MAX 2048

// ---------------- scratch (device globals; no allocation) ----------------
__device__ float4 g_fcwT[8192];          // fc_w transposed: [idx][k]
__device__ float4 g_A[16 * 1024];        // folded fc2+dconv1 weights: [oc*1024+px][k]
__device__ float  g_Beff[16 * 1024];     // folded bias
__device__ float  g_U[12 * 8];           // precomputed Rot gates

// ---------------- prep ----------------
__global__ void prep_kernel(const float* __restrict__ fc_w,
                            const float* __restrict__ fc2_w,
                            const float* __restrict__ fc2_b,
                            const float* __restrict__ dconv1_w,
                            const float* __restrict__ dconv1_b,
                            const float* __restrict__ qw)
{
    int i = blockIdx.x * blockDim.x + threadIdx.x;
    if (i < 12) {
        float phi = qw[i * 3 + 0], th = qw[i * 3 + 1], om = qw[i * 3 + 2];
        float ct = cosf(0.5f * th), st = sinf(0.5f * th);
        float a = 0.5f * (phi + om), d = 0.5f * (phi - om);
        float ca = cosf(a), sa = sinf(a), cd = cosf(d), sd = sinf(d);
        float* u = &g_U[i * 8];
        u[0] =  ca * ct;  u[1] = -sa * ct;
        u[2] = -cd * st;  u[3] = -sd * st;
        u[4] =  cd * st;  u[5] = -sd * st;
        u[6] =  ca * ct;  u[7] =  sa * ct;
    }
    if (i < 8192) {
        g_fcwT[i] = make_float4(fc_w[i], fc_w[8192 + i], fc_w[16384 + i], fc_w[24576 + i]);
    }
    if (i < 16 * 1024) {
        int oc = i >> 10, px = i & 1023, y = px >> 5, x = px & 31;
        float s0 = 0.f, s1 = 0.f, s2 = 0.f, s3 = 0.f;
        float bs = dconv1_b[oc];
        for (int c = 0; c < 8; c++) {
            for (int dy = 0; dy < 3; dy++) {
                int iy = y + dy - 1;
                if ((unsigned)iy >= 32u) continue;
                for (int dx = 0; dx < 3; dx++) {
                    int ix = x + dx - 1;
                    if ((unsigned)ix >= 32u) continue;
                    int idx = (c << 10) + (iy << 5) + ix;
                    float w = dconv1_w[((oc * 8 + c) * 3 + dy) * 3 + dx];
                    float4 f = reinterpret_cast<const float4*>(fc2_w)[idx];
                    s0 = fmaf(w, f.x, s0);
                    s1 = fmaf(w, f.y, s1);
                    s2 = fmaf(w, f.z, s2);
                    s3 = fmaf(w, f.w, s3);
                    bs = fmaf(w, fc2_b[idx], bs);
                }
            }
        }
        g_A[i] = make_float4(s0, s1, s2, s3);
        g_Beff[i] = bs;
    }
}

// halo helper: v0/v5 from neighbor lanes via shuffle (pad=0 at tile edge)
__device__ __forceinline__ void halo6(const float* base, int x0, int lane7,
                                      float v[6])
{
    float4 vm = *reinterpret_cast<const float4*>(base + 4 + x0);
    float v0 = __shfl_up_sync(0xffffffffu, vm.w, 1);
    float v5 = __shfl_down_sync(0xffffffffu, vm.x, 1);
    if (lane7 == 0) v0 = 0.f;
    if (lane7 == 7) v5 = 0.f;
    v[0] = v0; v[1] = vm.x; v[2] = vm.y; v[3] = vm.z; v[4] = vm.w; v[5] = v5;
}

// ============================================================================
// FUSED: conv1 -> conv2 -> fc -> quantum -> folded dconv1 -> dconv2 -> sigmoid
// 1 image per block. thread = (row y = t>>3, 4 contiguous px at x0=(t&7)*4)
// ============================================================================
struct FusedS {
    union {
        struct {
            float sx[3][34][40];    // padded input
            float sh1[4][34][40];   // padded conv1 group output
        } f;
        float sact[8][34][40];      // padded dconv1 group output (43.5KB)
    } u;
    float sw1[432];     // conv1 w
    float sw2[1152];    // conv2 w
    float swb[432];     // dconv2 w
    float sb1[16];
    float sb2[8];
    float sbb[3];
    float red[8][4];
    float ang[4];
    float qv[4];
};

__global__ __launch_bounds__(256, 3) void fused_kernel(
    const float* __restrict__ x,
    const float* __restrict__ w1, const float* __restrict__ b1,
    const float* __restrict__ w2, const float* __restrict__ b2,
    const float* __restrict__ fcb,
    const float* __restrict__ wb, const float* __restrict__ bb,
    float* __restrict__ out)
{
    extern __shared__ char raw[];
    FusedS& S = *reinterpret_cast<FusedS*>(raw);
    const int bidx = blockIdx.x, t = threadIdx.x;
    const int y = t >> 3, x0 = (t & 7) << 2;
    const int lane7 = t & 7;

    // ---------------- init smem ----------------
    {
        float4 z = make_float4(0.f, 0.f, 0.f, 0.f);
        float4* px4 = reinterpret_cast<float4*>(&S.u.f.sx[0][0][0]);
        for (int i = t; i < 3 * 34 * 10; i += 256) px4[i] = z;
        float4* ph4 = reinterpret_cast<float4*>(&S.u.f.sh1[0][0][0]);
        for (int i = t; i < 4 * 34 * 10; i += 256) ph4[i] = z;
    }
    for (int i = t; i < 432; i += 256) {
        int dx = i % 3, j = i / 3;
        int oc = j % 16, k = j / 16;
        int dy = k % 3, ic = k / 3;
        S.sw1[i] = w1[((oc * 3 + ic) * 3 + dy) * 3 + dx];
    }
    for (int i = t; i < 1152; i += 256) {
        int dx = i % 3, j = i / 3;
        int o = j % 8, k = j / 8;
        int dy = k % 3, ic = k / 3;
        S.sw2[i] = w2[((o * 16 + ic) * 3 + dy) * 3 + dx];
    }
    for (int i = t; i < 432; i += 256) {
        int dx = i % 3, j = i / 3;
        int o = j % 3, k = j / 3;
        int dy = k % 3, ic = k / 3;
        S.swb[i] = wb[((o * 16 + ic) * 3 + dy) * 3 + dx];
    }
    if (t < 16) S.sb1[t] = b1[t];
    if (t < 8)  S.sb2[t] = b2[t];
    if (t < 3)  S.sbb[t] = bb[t];
    __syncthreads();

    const float* xb = x + bidx * 3072;
    for (int i = t; i < 3072; i += 256) {
        int c = i >> 10, p = i & 1023;
        S.u.f.sx[c][1 + (p >> 5)][4 + (p & 31)] = xb[i];
    }
    __syncthreads();

    // ---------------- frontend: conv1 (4-oc groups) + conv2 ----------------
    float acc2[8][4];
    #pragma unroll
    for (int o = 0; o < 8; o++) {
        float b = S.sb2[o];
        #pragma unroll
        for (int p = 0; p < 4; p++) acc2[o][p] = b;
    }

    for (int g = 0; g < 4; g++) {
        float a1[4][4];
        #pragma unroll
        for (int o = 0; o < 4; o++) {
            float b = S.sb1[g * 4 + o];
            #pragma unroll
            for (int p = 0; p < 4; p++) a1[o][p] = b;
        }
        #pragma unroll
        for (int ic = 0; ic < 3; ic++)
            #pragma unroll
            for (int dy = 0; dy < 3; dy++) {
                float v[6];
                halo6(&S.u.f.sx[ic][y + dy][0], x0, lane7, v);
                #pragma unroll
                for (int o = 0; o < 4; o++) {
                    int wi = ((ic * 3 + dy) * 16 + g * 4 + o) * 3;
                    float w0 = S.sw1[wi], wA = S.sw1[wi + 1], wB = S.sw1[wi + 2];
                    #pragma unroll
                    for (int p = 0; p < 4; p++)
                        a1[o][p] = fmaf(v[p], w0, fmaf(v[p + 1], wA, fmaf(v[p + 2], wB, a1[o][p])));
                }
            }
        #pragma unroll
        for (int o = 0; o < 4; o++) {
            float4 r = make_float4(fmaxf(a1[o][0], 0.f), fmaxf(a1[o][1], 0.f),
                                   fmaxf(a1[o][2], 0.f), fmaxf(a1[o][3], 0.f));
            *reinterpret_cast<float4*>(&S.u.f.sh1[o][1 + y][4 + x0]) = r;
        }
        __syncthreads();

        #pragma unroll
        for (int icg = 0; icg < 4; icg++) {
            int ic16 = g * 4 + icg;
            #pragma unroll
            for (int dy = 0; dy < 3; dy++) {
                float v[6];
                halo6(&S.u.f.sh1[icg][y + dy][0], x0, lane7, v);
                #pragma unroll
                for (int o = 0; o < 8; o++) {
                    int wi = ((ic16 * 3 + dy) * 8 + o) * 3;
                    float w0 = S.sw2[wi], wA = S.sw2[wi + 1], wB = S.sw2[wi + 2];
                    #pragma unroll
                    for (int p = 0; p < 4; p++)
                        acc2[o][p] = fmaf(v[p], w0, fmaf(v[p + 1], wA, fmaf(v[p + 2], wB, acc2[o][p])));
                }
            }
        }
        __syncthreads();
    }

    // ---------------- relu + fc ----------------
    float angk[4] = {0.f, 0.f, 0.f, 0.f};
    #pragma unroll
    for (int o = 0; o < 8; o++) {
        #pragma unroll
        for (int p = 0; p < 4; p++) {
            float v = fmaxf(acc2[o][p], 0.f);
            float4 f = g_fcwT[(o << 10) + (y << 5) + x0 + p];
            angk[0] = fmaf(v, f.x, angk[0]);
            angk[1] = fmaf(v, f.y, angk[1]);
            angk[2] = fmaf(v, f.z, angk[2]);
            angk[3] = fmaf(v, f.w, angk[3]);
        }
    }
    #pragma unroll
    for (int k = 0; k < 4; k++)
        #pragma unroll
        for (int off = 16; off > 0; off >>= 1)
            angk[k] += __shfl_xor_sync(0xffffffffu, angk[k], off);
    {
        const int wrp = t >> 5, ln = t & 31;
        if (ln == 0) {
            #pragma unroll
            for (int k = 0; k < 4; k++) S.red[wrp][k] = angk[k];
        }
    }
    __syncthreads();
    if (t < 4) {
        float s = 0.f;
        #pragma unroll
        for (int w = 0; w < 8; w++) s += S.red[w][t];
        S.ang[t] = s + fcb[t];
    }
    __syncthreads();

    // ---------------- quantum (warp 0, redundant lanes) + pad re-zero ----------------
    if (t < 32) {
        float sr[16], si[16];
        #pragma unroll
        for (int i = 0; i < 16; i++) { sr[i] = 0.f; si[i] = 0.f; }
        sr[0] = 1.f;

        #pragma unroll
        for (int w = 0; w < 4; w++) {
            float h = 0.5f * S.ang[w];
            float c = cosf(h), s = sinf(h);
            const int bit = 1 << (3 - w);
            #pragma unroll
            for (int i = 0; i < 16; i++) {
                if (i & bit) continue;
                int j = i | bit;
                float ar = sr[i], ai = si[i], br = sr[j], bi = si[j];
                sr[i] = fmaf(c, ar,  s * bi);  si[i] = fmaf(c, ai, -s * br);
                sr[j] = fmaf(c, br,  s * ai);  si[j] = fmaf(c, bi, -s * ar);
            }
        }
        #pragma unroll
        for (int l = 0; l < 3; l++) {
            #pragma unroll
            for (int w = 0; w < 4; w++) {
                const float* u = &g_U[(l * 4 + w) * 8];
                float u00r = __ldg(u + 0), u00i = __ldg(u + 1);
                float u01r = __ldg(u + 2), u01i = __ldg(u + 3);
                float u10r = __ldg(u + 4), u10i = __ldg(u + 5);
                float u11r = __ldg(u + 6), u11i = __ldg(u + 7);
                const int bit = 1 << (3 - w);
                #pragma unroll
                for (int i = 0; i < 16; i++) {
                    if (i & bit) continue;
                    int j = i | bit;
                    float ar = sr[i], ai = si[i], br = sr[j], bi = si[j];
                    sr[i] = u00r * ar - u00i * ai + u01r * br - u01i * bi;
                    si[i] = u00r * ai + u00i * ar + u01r * bi + u01i * br;
                    sr[j] = u10r * ar - u10i * ai + u11r * br - u11i * bi;
                    si[j] = u10r * ai + u10i * ar + u11r * bi + u11i * br;
                }
            }
            const int r = (l % 3) + 1;
            #pragma unroll
            for (int w = 0; w < 4; w++) {
                int tq = (w + r) & 3;
                const int cb = 1 << (3 - w), tb = 1 << (3 - tq);
                #pragma unroll
                for (int i = 0; i < 16; i++) {
                    if ((i & cb) && !(i & tb)) {
                        int j = i | tb;
                        float tr = sr[i]; sr[i] = sr[j]; sr[j] = tr;
                        float ti = si[i]; si[i] = si[j]; si[j] = ti;
                    }
                }
            }
        }
        if (t < 4) {
            const int bit = 1 << (3 - t);
            float e = 0.f;
            #pragma unroll
            for (int i = 0; i < 16; i++) {
                float p = sr[i] * sr[i] + si[i] * si[i];
                e += (i & bit) ? -p : p;
            }
            S.qv[t] = e;
        }
    } else if (t < 32 + 160) {
        // re-zero sact padding rows 0 and 33 (union memory holds stale data)
        int i = t - 32;                 // 0..159 -> 8ch x 2 rows x 10 float4
        int ch = i / 20, rem = i % 20;
        int row = (rem < 10) ? 0 : 33;
        int c4 = rem % 10;
        reinterpret_cast<float4*>(&S.u.sact[ch][row][0])[c4] =
            make_float4(0.f, 0.f, 0.f, 0.f);
    }
    __syncthreads();

    // ---------------- backend ----------------
    const float q0 = S.qv[0], q1 = S.qv[1], q2 = S.qv[2], q3 = S.qv[3];

    float acc[3][4];
    #pragma unroll
    for (int o = 0; o < 3; o++) {
        float b = S.sbb[o];
        #pragma unroll
        for (int p = 0; p < 4; p++) acc[o][p] = b;
    }

    for (int g = 0; g < 2; g++) {
        // stage 1: folded dconv1, oc group g
        #pragma unroll 2
        for (int o8 = 0; o8 < 8; o8++) {
            int oc = g * 8 + o8;
            int idx = (oc << 10) + (y << 5) + x0;
            float4 a0 = g_A[idx], a1 = g_A[idx + 1], a2 = g_A[idx + 2], a3 = g_A[idx + 3];
            float4 be = *reinterpret_cast<const float4*>(&g_Beff[idx]);
            float v0 = fmaf(q0, a0.x, fmaf(q1, a0.y, fmaf(q2, a0.z, fmaf(q3, a0.w, be.x))));
            float v1 = fmaf(q0, a1.x, fmaf(q1, a1.y, fmaf(q2, a1.z, fmaf(q3, a1.w, be.y))));
            float v2 = fmaf(q0, a2.x, fmaf(q1, a2.y, fmaf(q2, a2.z, fmaf(q3, a2.w, be.z))));
            float v3 = fmaf(q0, a3.x, fmaf(q1, a3.y, fmaf(q2, a3.z, fmaf(q3, a3.w, be.w))));
            *reinterpret_cast<float4*>(&S.u.sact[o8][1 + y][4 + x0]) =
                make_float4(fmaxf(v0, 0.f), fmaxf(v1, 0.f), fmaxf(v2, 0.f), fmaxf(v3, 0.f));
        }
        __syncthreads();

        // stage 2: dconv2 partial over these 8 input channels
        #pragma unroll
        for (int icg = 0; icg < 8; icg++) {
            int ic16 = g * 8 + icg;
            #pragma unroll
            for (int dy = 0; dy < 3; dy++) {
                float v[6];
                halo6(&S.u.sact[icg][y + dy][0], x0, lane7, v);
                #pragma unroll
                for (int o = 0; o < 3; o++) {
                    int wi = ((ic16 * 3 + dy) * 3 + o) * 3;
                    float w0 = S.swb[wi], wA = S.swb[wi + 1], wB = S.swb[wi + 2];
                    #pragma unroll
                    for (int p = 0; p < 4; p++)
                        acc[o][p] = fmaf(v[p], w0, fmaf(v[p + 1], wA, fmaf(v[p + 2], wB, acc[o][p])));
                }
            }
        }
        __syncthreads();
    }

    // ---------------- sigmoid epilogue ----------------
    float* ob = out + bidx * 3072;
    #pragma unroll
    for (int o = 0; o < 3; o++) {
        float4 r = make_float4(1.f / (1.f + __expf(-acc[o][0])),
                               1.f / (1.f + __expf(-acc[o][1])),
                               1.f / (1.f + __expf(-acc[o][2])),
                               1.f / (1.f + __expf(-acc[o][3])));
        *reinterpret_cast<float4*>(&ob[(o << 10) + (y << 5) + x0]) = r;
    }
}

// ---------------- launch ----------------
extern "C" void kernel_launch(void* const* d_in, const int* in_sizes, int n_in,
                              void* d_out, int out_size)
{
    const float* x        = (const float*)d_in[0];
    const float* conv1_w  = (const float*)d_in[1];
    const float* conv1_b  = (const float*)d_in[2];
    const float* conv2_w  = (const float*)d_in[3];
    const float* conv2_b  = (const float*)d_in[4];
    const float* fc_w     = (const float*)d_in[5];
    const float* fc_b     = (const float*)d_in[6];
    const float* q_w      = (const float*)d_in[7];
    const float* fc2_w    = (const float*)d_in[8];
    const float* fc2_b    = (const float*)d_in[9];
    const float* dconv1_w = (const float*)d_in[10];
    const float* dconv1_b = (const float*)d_in[11];
    const float* dconv2_w = (const float*)d_in[12];
    const float* dconv2_b = (const float*)d_in[13];
    float* out = (float*)d_out;

    const int batch = in_sizes[0] / (3 * 32 * 32);

    cudaFuncSetAttribute(fused_kernel, cudaFuncAttributeMaxDynamicSharedMemorySize,
                         (int)sizeof(FusedS));

    prep_kernel<<<64, 256>>>(fc_w, fc2_w, fc2_b, dconv1_w, dconv1_b, q_w);
    fused_kernel<<<batch, 256, sizeof(FusedS)>>>(x, conv1_w, conv1_b,
                                                 conv2_w, conv2_b, fc_b,
                                                 dconv2_w, dconv2_b, out);
}

// round 7
// speedup vs baseline: 1.1770x; 1.1770x over previous
#include <cuda_runtime.h>
#include <math.h>

#define BATCH_MAX 2048

// ---------------- constant weights (block-invariant, ~8KB total) ----------------
__constant__ float c_w1[432];    // conv1 (16,3,3,3)  original layout
__constant__ float c_b1[16];
__constant__ float c_w2[1152];   // conv2 (8,16,3,3)
__constant__ float c_b2[8];
__constant__ float c_fcb[4];
__constant__ float c_wb[432];    // dconv2 (3,16,3,3)
__constant__ float c_bb[3];

// ---------------- scratch (device globals; no allocation) ----------------
__device__ float4 g_fcwT[8192];          // fc_w transposed: [idx][k]
__device__ float4 g_A[16 * 1024];        // folded fc2+dconv1 weights
__device__ float  g_Beff[16 * 1024];     // folded bias
__device__ float  g_ang[BATCH_MAX * 4];
__device__ float  g_q[BATCH_MAX * 4];
__device__ float  g_U[12 * 8];           // precomputed Rot gates

// ---------------- prep ----------------
__global__ void prep_kernel(const float* __restrict__ fc_w,
                            const float* __restrict__ fc2_w,
                            const float* __restrict__ fc2_b,
                            const float* __restrict__ dconv1_w,
                            const float* __restrict__ dconv1_b,
                            const float* __restrict__ qw)
{
    int i = blockIdx.x * blockDim.x + threadIdx.x;
    if (i < 12) {
        float phi = qw[i * 3 + 0], th = qw[i * 3 + 1], om = qw[i * 3 + 2];
        float ct = cosf(0.5f * th), st = sinf(0.5f * th);
        float a = 0.5f * (phi + om), d = 0.5f * (phi - om);
        float ca = cosf(a), sa = sinf(a), cd = cosf(d), sd = sinf(d);
        float* u = &g_U[i * 8];
        u[0] =  ca * ct;  u[1] = -sa * ct;
        u[2] = -cd * st;  u[3] = -sd * st;
        u[4] =  cd * st;  u[5] = -sd * st;
        u[6] =  ca * ct;  u[7] =  sa * ct;
    }
    if (i < 8192) {
        g_fcwT[i] = make_float4(fc_w[i], fc_w[8192 + i], fc_w[16384 + i], fc_w[24576 + i]);
    }
    if (i < 16 * 1024) {
        int oc = i >> 10, px = i & 1023, y = px >> 5, x = px & 31;
        float s0 = 0.f, s1 = 0.f, s2 = 0.f, s3 = 0.f;
        float bs = dconv1_b[oc];
        for (int c = 0; c < 8; c++) {
            for (int dy = 0; dy < 3; dy++) {
                int iy = y + dy - 1;
                if ((unsigned)iy >= 32u) continue;
                for (int dx = 0; dx < 3; dx++) {
                    int ix = x + dx - 1;
                    if ((unsigned)ix >= 32u) continue;
                    int idx = (c << 10) + (iy << 5) + ix;
                    float w = dconv1_w[((oc * 8 + c) * 3 + dy) * 3 + dx];
                    float4 f = reinterpret_cast<const float4*>(fc2_w)[idx];
                    s0 = fmaf(w, f.x, s0);
                    s1 = fmaf(w, f.y, s1);
                    s2 = fmaf(w, f.z, s2);
                    s3 = fmaf(w, f.w, s3);
                    bs = fmaf(w, fc2_b[idx], bs);
                }
            }
        }
        g_A[i] = make_float4(s0, s1, s2, s3);
        g_Beff[i] = bs;
    }
}

// halo helper: v0/v5 from neighbor lanes via shuffle (pad=0 at tile edge)
__device__ __forceinline__ void halo6(const float* base, int x0, int lane7,
                                      float v[6])
{
    float4 vm = *reinterpret_cast<const float4*>(base + 4 + x0);
    float v0 = __shfl_up_sync(0xffffffffu, vm.w, 1);
    float v5 = __shfl_down_sync(0xffffffffu, vm.x, 1);
    if (lane7 == 0) v0 = 0.f;
    if (lane7 == 7) v5 = 0.f;
    v[0] = v0; v[1] = vm.x; v[2] = vm.y; v[3] = vm.z; v[4] = vm.w; v[5] = v5;
}

// ============================================================================
// FRONTEND: conv1(4-oc groups)+relu -> conv2+relu -> fc.  Weights in constant.
// thread = (row y = t>>3, 4 contiguous px at x0 = (t&7)*4)
// ============================================================================
struct FrontS {
    float sx[3][34][40];
    float sh1[4][34][40];
    float red[8][4];
};

__global__ __launch_bounds__(256, 3) void frontend_kernel(
    const float* __restrict__ x)
{
    extern __shared__ char raw[];
    FrontS& S = *reinterpret_cast<FrontS*>(raw);
    const int bidx = blockIdx.x, t = threadIdx.x;
    const int y = t >> 3, x0 = (t & 7) << 2;
    const int lane7 = t & 7;

    {
        float4 z = make_float4(0.f, 0.f, 0.f, 0.f);
        float4* px4 = reinterpret_cast<float4*>(&S.sx[0][0][0]);
        for (int i = t; i < 3 * 34 * 10; i += 256) px4[i] = z;
        float4* ph4 = reinterpret_cast<float4*>(&S.sh1[0][0][0]);
        for (int i = t; i < 4 * 34 * 10; i += 256) ph4[i] = z;
    }
    __syncthreads();

    const float* xb = x + bidx * 3072;
    for (int i = t; i < 3072; i += 256) {
        int c = i >> 10, p = i & 1023;
        S.sx[c][1 + (p >> 5)][4 + (p & 31)] = xb[i];
    }
    __syncthreads();

    float acc2[8][4];
    #pragma unroll
    for (int o = 0; o < 8; o++) {
        float b = c_b2[o];
        #pragma unroll
        for (int p = 0; p < 4; p++) acc2[o][p] = b;
    }

    #pragma unroll 1
    for (int g = 0; g < 4; g++) {
        // ---- conv1, oc group g (4 oc) ----
        float a1[4][4];
        #pragma unroll
        for (int o = 0; o < 4; o++) {
            float b = c_b1[g * 4 + o];
            #pragma unroll
            for (int p = 0; p < 4; p++) a1[o][p] = b;
        }
        #pragma unroll
        for (int ic = 0; ic < 3; ic++)
            #pragma unroll
            for (int dy = 0; dy < 3; dy++) {
                float v[6];
                halo6(&S.sx[ic][y + dy][0], x0, lane7, v);
                #pragma unroll
                for (int o = 0; o < 4; o++) {
                    // conv1 original layout: (oc,ic,dy,dx)
                    const float* wp = &c_w1[(((g * 4 + o) * 3 + ic) * 3 + dy) * 3];
                    float w0 = wp[0], wA = wp[1], wB = wp[2];
                    #pragma unroll
                    for (int p = 0; p < 4; p++)
                        a1[o][p] = fmaf(v[p], w0, fmaf(v[p + 1], wA, fmaf(v[p + 2], wB, a1[o][p])));
                }
            }
        #pragma unroll
        for (int o = 0; o < 4; o++) {
            float4 r = make_float4(fmaxf(a1[o][0], 0.f), fmaxf(a1[o][1], 0.f),
                                   fmaxf(a1[o][2], 0.f), fmaxf(a1[o][3], 0.f));
            *reinterpret_cast<float4*>(&S.sh1[o][1 + y][4 + x0]) = r;
        }
        __syncthreads();

        // ---- conv2 partial over these 4 input channels ----
        #pragma unroll
        for (int icg = 0; icg < 4; icg++) {
            int ic16 = g * 4 + icg;
            #pragma unroll
            for (int dy = 0; dy < 3; dy++) {
                float v[6];
                halo6(&S.sh1[icg][y + dy][0], x0, lane7, v);
                #pragma unroll
                for (int o = 0; o < 8; o++) {
                    // conv2 original layout: (o,ic,dy,dx)
                    const float* wp = &c_w2[((o * 16 + ic16) * 3 + dy) * 3];
                    float w0 = wp[0], wA = wp[1], wB = wp[2];
                    #pragma unroll
                    for (int p = 0; p < 4; p++)
                        acc2[o][p] = fmaf(v[p], w0, fmaf(v[p + 1], wA, fmaf(v[p + 2], wB, acc2[o][p])));
                }
            }
        }
        __syncthreads();
    }

    // ---- relu + fc ----
    float angk[4] = {0.f, 0.f, 0.f, 0.f};
    #pragma unroll
    for (int o = 0; o < 8; o++) {
        #pragma unroll
        for (int p = 0; p < 4; p++) {
            float v = fmaxf(acc2[o][p], 0.f);
            float4 f = g_fcwT[(o << 10) + (y << 5) + x0 + p];
            angk[0] = fmaf(v, f.x, angk[0]);
            angk[1] = fmaf(v, f.y, angk[1]);
            angk[2] = fmaf(v, f.z, angk[2]);
            angk[3] = fmaf(v, f.w, angk[3]);
        }
    }
    #pragma unroll
    for (int k = 0; k < 4; k++)
        #pragma unroll
        for (int off = 16; off > 0; off >>= 1)
            angk[k] += __shfl_xor_sync(0xffffffffu, angk[k], off);
    const int wrp = t >> 5, ln = t & 31;
    if (ln == 0) {
        #pragma unroll
        for (int k = 0; k < 4; k++) S.red[wrp][k] = angk[k];
    }
    __syncthreads();
    if (t < 4) {
        float s = 0.f;
        #pragma unroll
        for (int w = 0; w < 8; w++) s += S.red[w][t];
        g_ang[bidx * 4 + t] = s + c_fcb[t];
    }
}

// ---------------- quantum ----------------
__global__ void quantum_kernel(int batch)
{
    int b = blockIdx.x * blockDim.x + threadIdx.x;
    if (b >= batch) return;

    float sr[16], si[16];
    #pragma unroll
    for (int i = 0; i < 16; i++) { sr[i] = 0.f; si[i] = 0.f; }
    sr[0] = 1.f;

    #pragma unroll
    for (int w = 0; w < 4; w++) {
        float h = 0.5f * g_ang[b * 4 + w];
        float c = cosf(h), s = sinf(h);
        const int bit = 1 << (3 - w);
        #pragma unroll
        for (int i = 0; i < 16; i++) {
            if (i & bit) continue;
            int j = i | bit;
            float ar = sr[i], ai = si[i], br = sr[j], bi = si[j];
            sr[i] = fmaf(c, ar,  s * bi);  si[i] = fmaf(c, ai, -s * br);
            sr[j] = fmaf(c, br,  s * ai);  si[j] = fmaf(c, bi, -s * ar);
        }
    }

    #pragma unroll
    for (int l = 0; l < 3; l++) {
        #pragma unroll
        for (int w = 0; w < 4; w++) {
            const float* u = &g_U[(l * 4 + w) * 8];
            float u00r = u[0], u00i = u[1], u01r = u[2], u01i = u[3];
            float u10r = u[4], u10i = u[5], u11r = u[6], u11i = u[7];
            const int bit = 1 << (3 - w);
            #pragma unroll
            for (int i = 0; i < 16; i++) {
                if (i & bit) continue;
                int j = i | bit;
                float ar = sr[i], ai = si[i], br = sr[j], bi = si[j];
                sr[i] = u00r * ar - u00i * ai + u01r * br - u01i * bi;
                si[i] = u00r * ai + u00i * ar + u01r * bi + u01i * br;
                sr[j] = u10r * ar - u10i * ai + u11r * br - u11i * bi;
                si[j] = u10r * ai + u10i * ar + u11r * bi + u11i * br;
            }
        }
        const int r = (l % 3) + 1;
        #pragma unroll
        for (int w = 0; w < 4; w++) {
            int tq = (w + r) & 3;
            const int cb = 1 << (3 - w), tb = 1 << (3 - tq);
            #pragma unroll
            for (int i = 0; i < 16; i++) {
                if ((i & cb) && !(i & tb)) {
                    int j = i | tb;
                    float tr = sr[i]; sr[i] = sr[j]; sr[j] = tr;
                    float ti = si[i]; si[i] = si[j]; si[j] = ti;
                }
            }
        }
    }

    #pragma unroll
    for (int w = 0; w < 4; w++) {
        const int bit = 1 << (3 - w);
        float e = 0.f;
        #pragma unroll
        for (int i = 0; i < 16; i++) {
            float p = sr[i] * sr[i] + si[i] * si[i];
            e += (i & bit) ? -p : p;
        }
        g_q[b * 4 + w] = e;
    }
}

// ============================================================================
// BACKEND: folded dconv1 + relu -> dconv2 + sigmoid.  2 images/block.
// Weights in constant.
// ============================================================================
struct BackS {
    float sact[2][8][34][40];  // 87,040 B
};

__global__ __launch_bounds__(256, 2) void backend_kernel(float* __restrict__ out)
{
    extern __shared__ char raw[];
    BackS& S = *reinterpret_cast<BackS*>(raw);
    const int bid = blockIdx.x, t = threadIdx.x;
    const int b0 = 2 * bid;
    const int y = t >> 3, x0 = (t & 7) << 2;
    const int lane7 = t & 7;

    {
        float4 z = make_float4(0.f, 0.f, 0.f, 0.f);
        float4* p4 = reinterpret_cast<float4*>(&S.sact[0][0][0][0]);
        for (int i = t; i < 2 * 8 * 34 * 10; i += 256) p4[i] = z;
    }

    float qa[4], qb[4];
    #pragma unroll
    for (int k = 0; k < 4; k++) {
        qa[k] = g_q[b0 * 4 + k];
        qb[k] = g_q[(b0 + 1) * 4 + k];
    }
    __syncthreads();

    float acc[2][3][4];
    #pragma unroll
    for (int o = 0; o < 3; o++) {
        float b = c_bb[o];
        #pragma unroll
        for (int p = 0; p < 4; p++) { acc[0][o][p] = b; acc[1][o][p] = b; }
    }

    #pragma unroll 1
    for (int g = 0; g < 2; g++) {
        // ---- stage 1: folded dconv1, oc group g, both images ----
        #pragma unroll 2
        for (int o8 = 0; o8 < 8; o8++) {
            int oc = g * 8 + o8;
            int idx = (oc << 10) + (y << 5) + x0;
            float4 a0 = g_A[idx], a1 = g_A[idx + 1], a2 = g_A[idx + 2], a3 = g_A[idx + 3];
            float4 be = *reinterpret_cast<const float4*>(&g_Beff[idx]);
            {
                float v0 = fmaf(qa[0], a0.x, fmaf(qa[1], a0.y, fmaf(qa[2], a0.z, fmaf(qa[3], a0.w, be.x))));
                float v1 = fmaf(qa[0], a1.x, fmaf(qa[1], a1.y, fmaf(qa[2], a1.z, fmaf(qa[3], a1.w, be.y))));
                float v2 = fmaf(qa[0], a2.x, fmaf(qa[1], a2.y, fmaf(qa[2], a2.z, fmaf(qa[3], a2.w, be.z))));
                float v3 = fmaf(qa[0], a3.x, fmaf(qa[1], a3.y, fmaf(qa[2], a3.z, fmaf(qa[3], a3.w, be.w))));
                *reinterpret_cast<float4*>(&S.sact[0][o8][1 + y][4 + x0]) =
                    make_float4(fmaxf(v0, 0.f), fmaxf(v1, 0.f), fmaxf(v2, 0.f), fmaxf(v3, 0.f));
            }
            {
                float v0 = fmaf(qb[0], a0.x, fmaf(qb[1], a0.y, fmaf(qb[2], a0.z, fmaf(qb[3], a0.w, be.x))));
                float v1 = fmaf(qb[0], a1.x, fmaf(qb[1], a1.y, fmaf(qb[2], a1.z, fmaf(qb[3], a1.w, be.y))));
                float v2 = fmaf(qb[0], a2.x, fmaf(qb[1], a2.y, fmaf(qb[2], a2.z, fmaf(qb[3], a2.w, be.z))));
                float v3 = fmaf(qb[0], a3.x, fmaf(qb[1], a3.y, fmaf(qb[2], a3.z, fmaf(qb[3], a3.w, be.w))));
                *reinterpret_cast<float4*>(&S.sact[1][o8][1 + y][4 + x0]) =
                    make_float4(fmaxf(v0, 0.f), fmaxf(v1, 0.f), fmaxf(v2, 0.f), fmaxf(v3, 0.f));
            }
        }
        __syncthreads();

        // ---- stage 2: dconv2 partial, both images ----
        #pragma unroll
        for (int img = 0; img < 2; img++) {
            #pragma unroll
            for (int icg = 0; icg < 8; icg++) {
                int ic16 = g * 8 + icg;
                #pragma unroll
                for (int dy = 0; dy < 3; dy++) {
                    float v[6];
                    halo6(&S.sact[img][icg][y + dy][0], x0, lane7, v);
                    #pragma unroll
                    for (int o = 0; o < 3; o++) {
                        // dconv2 original layout: (o,ic,dy,dx)
                        const float* wp = &c_wb[((o * 16 + ic16) * 3 + dy) * 3];
                        float w0 = wp[0], wA = wp[1], wB = wp[2];
                        #pragma unroll
                        for (int p = 0; p < 4; p++)
                            acc[img][o][p] = fmaf(v[p], w0,
                                fmaf(v[p + 1], wA, fmaf(v[p + 2], wB, acc[img][o][p])));
                    }
                }
            }
        }
        __syncthreads();
    }

    // ---- sigmoid epilogue, both images ----
    #pragma unroll
    for (int img = 0; img < 2; img++) {
        float* ob = out + (b0 + img) * 3072;
        #pragma unroll
        for (int o = 0; o < 3; o++) {
            float4 r = make_float4(1.f / (1.f + __expf(-acc[img][o][0])),
                                   1.f / (1.f + __expf(-acc[img][o][1])),
                                   1.f / (1.f + __expf(-acc[img][o][2])),
                                   1.f / (1.f + __expf(-acc[img][o][3])));
            *reinterpret_cast<float4*>(&ob[(o << 10) + (y << 5) + x0]) = r;
        }
    }
}

// ---------------- launch ----------------
extern "C" void kernel_launch(void* const* d_in, const int* in_sizes, int n_in,
                              void* d_out, int out_size)
{
    const float* x        = (const float*)d_in[0];
    const float* conv1_w  = (const float*)d_in[1];
    const float* conv1_b  = (const float*)d_in[2];
    const float* conv2_w  = (const float*)d_in[3];
    const float* conv2_b  = (const float*)d_in[4];
    const float* fc_w     = (const float*)d_in[5];
    const float* fc_b     = (const float*)d_in[6];
    const float* q_w      = (const float*)d_in[7];
    const float* fc2_w    = (const float*)d_in[8];
    const float* fc2_b    = (const float*)d_in[9];
    const float* dconv1_w = (const float*)d_in[10];
    const float* dconv1_b = (const float*)d_in[11];
    const float* dconv2_w = (const float*)d_in[12];
    const float* dconv2_b = (const float*)d_in[13];
    float* out = (float*)d_out;

    const int batch = in_sizes[0] / (3 * 32 * 32);

    // stage weights into constant memory (D2D async copies; graph-capturable)
    cudaMemcpyToSymbolAsync(c_w1, conv1_w, 432 * sizeof(float), 0, cudaMemcpyDeviceToDevice);
    cudaMemcpyToSymbolAsync(c_b1, conv1_b, 16 * sizeof(float), 0, cudaMemcpyDeviceToDevice);
    cudaMemcpyToSymbolAsync(c_w2, conv2_w, 1152 * sizeof(float), 0, cudaMemcpyDeviceToDevice);
    cudaMemcpyToSymbolAsync(c_b2, conv2_b, 8 * sizeof(float), 0, cudaMemcpyDeviceToDevice);
    cudaMemcpyToSymbolAsync(c_fcb, fc_b, 4 * sizeof(float), 0, cudaMemcpyDeviceToDevice);
    cudaMemcpyToSymbolAsync(c_wb, dconv2_w, 432 * sizeof(float), 0, cudaMemcpyDeviceToDevice);
    cudaMemcpyToSymbolAsync(c_bb, dconv2_b, 3 * sizeof(float), 0, cudaMemcpyDeviceToDevice);

    cudaFuncSetAttribute(frontend_kernel, cudaFuncAttributeMaxDynamicSharedMemorySize,
                         (int)sizeof(FrontS));
    cudaFuncSetAttribute(backend_kernel, cudaFuncAttributeMaxDynamicSharedMemorySize,
                         (int)sizeof(BackS));

    prep_kernel<<<64, 256>>>(fc_w, fc2_w, fc2_b, dconv1_w, dconv1_b, q_w);
    frontend_kernel<<<batch, 256, sizeof(FrontS)>>>(x);
    quantum_kernel<<<(batch + 255) / 256, 256>>>(batch);
    backend_kernel<<<batch / 2, 256, sizeof(BackS)>>>(out);
}

// round 8
// speedup vs baseline: 1.2190x; 1.0356x over previous
#include <cuda_runtime.h>
#include <math.h>

#define BATCH_MAX 2048

// ---------------- constant weights (block-invariant, ~8KB total) ----------------
__constant__ float c_w1[432];    // conv1 (16,3,3,3)
__constant__ float c_b1[16];
__constant__ float c_w2[1152];   // conv2 (8,16,3,3)
__constant__ float c_b2[8];
__constant__ float c_fcb[4];
__constant__ float c_wb[432];    // dconv2 (3,16,3,3)
__constant__ float c_bb[3];

// ---------------- scratch (device globals; no allocation) ----------------
__device__ float4 g_fcwT[8192];
__device__ float4 g_A[16 * 1024];
__device__ float  g_Beff[16 * 1024];
__device__ float  g_ang[BATCH_MAX * 4];
__device__ float  g_q[BATCH_MAX * 4];
__device__ float  g_U[12 * 8];

// ---------------- prep ----------------
__global__ void prep_kernel(const float* __restrict__ fc_w,
                            const float* __restrict__ fc2_w,
                            const float* __restrict__ fc2_b,
                            const float* __restrict__ dconv1_w,
                            const float* __restrict__ dconv1_b,
                            const float* __restrict__ qw)
{
    int i = blockIdx.x * blockDim.x + threadIdx.x;
    if (i < 12) {
        float phi = qw[i * 3 + 0], th = qw[i * 3 + 1], om = qw[i * 3 + 2];
        float ct = cosf(0.5f * th), st = sinf(0.5f * th);
        float a = 0.5f * (phi + om), d = 0.5f * (phi - om);
        float ca = cosf(a), sa = sinf(a), cd = cosf(d), sd = sinf(d);
        float* u = &g_U[i * 8];
        u[0] =  ca * ct;  u[1] = -sa * ct;
        u[2] = -cd * st;  u[3] = -sd * st;
        u[4] =  cd * st;  u[5] = -sd * st;
        u[6] =  ca * ct;  u[7] =  sa * ct;
    }
    if (i < 8192) {
        g_fcwT[i] = make_float4(fc_w[i], fc_w[8192 + i], fc_w[16384 + i], fc_w[24576 + i]);
    }
    if (i < 16 * 1024) {
        int oc = i >> 10, px = i & 1023, y = px >> 5, x = px & 31;
        float s0 = 0.f, s1 = 0.f, s2 = 0.f, s3 = 0.f;
        float bs = dconv1_b[oc];
        for (int c = 0; c < 8; c++) {
            for (int dy = 0; dy < 3; dy++) {
                int iy = y + dy - 1;
                if ((unsigned)iy >= 32u) continue;
                for (int dx = 0; dx < 3; dx++) {
                    int ix = x + dx - 1;
                    if ((unsigned)ix >= 32u) continue;
                    int idx = (c << 10) + (iy << 5) + ix;
                    float w = dconv1_w[((oc * 8 + c) * 3 + dy) * 3 + dx];
                    float4 f = reinterpret_cast<const float4*>(fc2_w)[idx];
                    s0 = fmaf(w, f.x, s0);
                    s1 = fmaf(w, f.y, s1);
                    s2 = fmaf(w, f.z, s2);
                    s3 = fmaf(w, f.w, s3);
                    bs = fmaf(w, fc2_b[idx], bs);
                }
            }
        }
        g_A[i] = make_float4(s0, s1, s2, s3);
        g_Beff[i] = bs;
    }
}

// halo helper, stride-32 rows (no horizontal padding): row base + x0,
// v0/v5 from neighbor lanes via shuffle (pad=0 at tile edge)
__device__ __forceinline__ void halo6(const float* rowbase, int x0, int lane7,
                                      float v[6])
{
    float4 vm = *reinterpret_cast<const float4*>(rowbase + x0);
    float v0 = __shfl_up_sync(0xffffffffu, vm.w, 1);
    float v5 = __shfl_down_sync(0xffffffffu, vm.x, 1);
    if (lane7 == 0) v0 = 0.f;
    if (lane7 == 7) v5 = 0.f;
    v[0] = v0; v[1] = vm.x; v[2] = vm.y; v[3] = vm.z; v[4] = vm.w; v[5] = v5;
}

// ============================================================================
// FRONTEND: conv1(4-oc groups)+relu -> conv2+relu -> fc.
// thread = (row y = t>>3, 4 contiguous px at x0 = (t&7)*4).  Row stride 32.
// ============================================================================
struct FrontS {
    float sx[3][34][32];    // rows 0,33 = zero padding; data rows 1..32
    float sh1[4][34][32];
    float red[8][4];
};

__global__ __launch_bounds__(256, 3) void frontend_kernel(
    const float* __restrict__ x)
{
    extern __shared__ char raw[];
    FrontS& S = *reinterpret_cast<FrontS*>(raw);
    const int bidx = blockIdx.x, t = threadIdx.x;
    const int y = t >> 3, x0 = (t & 7) << 2;
    const int lane7 = t & 7;

    // zero only the vertical padding rows (rows 0 and 33)
    if (t < 112) {  // 3ch*2rows*8 + 4ch*2rows*8 = 48+64 float4
        float4 z = make_float4(0.f, 0.f, 0.f, 0.f);
        if (t < 48) {
            int ch = t / 16, rem = t % 16;
            int row = (rem < 8) ? 0 : 33, c4 = rem % 8;
            reinterpret_cast<float4*>(&S.sx[ch][row][0])[c4] = z;
        } else {
            int i = t - 48;
            int ch = i / 16, rem = i % 16;
            int row = (rem < 8) ? 0 : 33, c4 = rem % 8;
            reinterpret_cast<float4*>(&S.sh1[ch][row][0])[c4] = z;
        }
    }
    __syncthreads();

    const float* xb = x + bidx * 3072;
    for (int i = t; i < 768; i += 256) {   // 3072 floats = 768 float4
        int c = i / 256, p = i % 256;      // p indexes float4 within 32x32 image
        reinterpret_cast<float4*>(&S.sx[c][1][0])[p] =
            reinterpret_cast<const float4*>(xb)[i];
    }
    __syncthreads();

    float acc2[8][4];
    #pragma unroll
    for (int o = 0; o < 8; o++) {
        float b = c_b2[o];
        #pragma unroll
        for (int p = 0; p < 4; p++) acc2[o][p] = b;
    }

    #pragma unroll 1
    for (int g = 0; g < 4; g++) {
        // ---- conv1, oc group g (4 oc) ----
        float a1[4][4];
        #pragma unroll
        for (int o = 0; o < 4; o++) {
            float b = c_b1[g * 4 + o];
            #pragma unroll
            for (int p = 0; p < 4; p++) a1[o][p] = b;
        }
        #pragma unroll
        for (int ic = 0; ic < 3; ic++)
            #pragma unroll
            for (int dy = 0; dy < 3; dy++) {
                float v[6];
                halo6(&S.sx[ic][y + dy][0], x0, lane7, v);
                #pragma unroll
                for (int o = 0; o < 4; o++) {
                    const float* wp = &c_w1[(((g * 4 + o) * 3 + ic) * 3 + dy) * 3];
                    float w0 = wp[0], wA = wp[1], wB = wp[2];
                    #pragma unroll
                    for (int p = 0; p < 4; p++)
                        a1[o][p] = fmaf(v[p], w0, fmaf(v[p + 1], wA, fmaf(v[p + 2], wB, a1[o][p])));
                }
            }
        #pragma unroll
        for (int o = 0; o < 4; o++) {
            float4 r = make_float4(fmaxf(a1[o][0], 0.f), fmaxf(a1[o][1], 0.f),
                                   fmaxf(a1[o][2], 0.f), fmaxf(a1[o][3], 0.f));
            *reinterpret_cast<float4*>(&S.sh1[o][1 + y][x0]) = r;
        }
        __syncthreads();

        // ---- conv2 partial over these 4 input channels ----
        #pragma unroll
        for (int icg = 0; icg < 4; icg++) {
            int ic16 = g * 4 + icg;
            #pragma unroll
            for (int dy = 0; dy < 3; dy++) {
                float v[6];
                halo6(&S.sh1[icg][y + dy][0], x0, lane7, v);
                #pragma unroll
                for (int o = 0; o < 8; o++) {
                    const float* wp = &c_w2[((o * 16 + ic16) * 3 + dy) * 3];
                    float w0 = wp[0], wA = wp[1], wB = wp[2];
                    #pragma unroll
                    for (int p = 0; p < 4; p++)
                        acc2[o][p] = fmaf(v[p], w0, fmaf(v[p + 1], wA, fmaf(v[p + 2], wB, acc2[o][p])));
                }
            }
        }
        __syncthreads();
    }

    // ---- relu + fc ----
    float angk[4] = {0.f, 0.f, 0.f, 0.f};
    #pragma unroll
    for (int o = 0; o < 8; o++) {
        #pragma unroll
        for (int p = 0; p < 4; p++) {
            float v = fmaxf(acc2[o][p], 0.f);
            float4 f = g_fcwT[(o << 10) + (y << 5) + x0 + p];
            angk[0] = fmaf(v, f.x, angk[0]);
            angk[1] = fmaf(v, f.y, angk[1]);
            angk[2] = fmaf(v, f.z, angk[2]);
            angk[3] = fmaf(v, f.w, angk[3]);
        }
    }
    #pragma unroll
    for (int k = 0; k < 4; k++)
        #pragma unroll
        for (int off = 16; off > 0; off >>= 1)
            angk[k] += __shfl_xor_sync(0xffffffffu, angk[k], off);
    const int wrp = t >> 5, ln = t & 31;
    if (ln == 0) {
        #pragma unroll
        for (int k = 0; k < 4; k++) S.red[wrp][k] = angk[k];
    }
    __syncthreads();
    if (t < 4) {
        float s = 0.f;
        #pragma unroll
        for (int w = 0; w < 8; w++) s += S.red[w][t];
        g_ang[bidx * 4 + t] = s + c_fcb[t];
    }
}

// ---------------- quantum ----------------
__global__ void quantum_kernel(int batch)
{
    int b = blockIdx.x * blockDim.x + threadIdx.x;
    if (b >= batch) return;

    float sr[16], si[16];
    #pragma unroll
    for (int i = 0; i < 16; i++) { sr[i] = 0.f; si[i] = 0.f; }
    sr[0] = 1.f;

    #pragma unroll
    for (int w = 0; w < 4; w++) {
        float h = 0.5f * g_ang[b * 4 + w];
        float c = cosf(h), s = sinf(h);
        const int bit = 1 << (3 - w);
        #pragma unroll
        for (int i = 0; i < 16; i++) {
            if (i & bit) continue;
            int j = i | bit;
            float ar = sr[i], ai = si[i], br = sr[j], bi = si[j];
            sr[i] = fmaf(c, ar,  s * bi);  si[i] = fmaf(c, ai, -s * br);
            sr[j] = fmaf(c, br,  s * ai);  si[j] = fmaf(c, bi, -s * ar);
        }
    }

    #pragma unroll
    for (int l = 0; l < 3; l++) {
        #pragma unroll
        for (int w = 0; w < 4; w++) {
            const float* u = &g_U[(l * 4 + w) * 8];
            float u00r = u[0], u00i = u[1], u01r = u[2], u01i = u[3];
            float u10r = u[4], u10i = u[5], u11r = u[6], u11i = u[7];
            const int bit = 1 << (3 - w);
            #pragma unroll
            for (int i = 0; i < 16; i++) {
                if (i & bit) continue;
                int j = i | bit;
                float ar = sr[i], ai = si[i], br = sr[j], bi = si[j];
                sr[i] = u00r * ar - u00i * ai + u01r * br - u01i * bi;
                si[i] = u00r * ai + u00i * ar + u01r * bi + u01i * br;
                sr[j] = u10r * ar - u10i * ai + u11r * br - u11i * bi;
                si[j] = u10r * ai + u10i * ar + u11r * bi + u11i * br;
            }
        }
        const int r = (l % 3) + 1;
        #pragma unroll
        for (int w = 0; w < 4; w++) {
            int tq = (w + r) & 3;
            const int cb = 1 << (3 - w), tb = 1 << (3 - tq);
            #pragma unroll
            for (int i = 0; i < 16; i++) {
                if ((i & cb) && !(i & tb)) {
                    int j = i | tb;
                    float tr = sr[i]; sr[i] = sr[j]; sr[j] = tr;
                    float ti = si[i]; si[i] = si[j]; si[j] = ti;
                }
            }
        }
    }

    #pragma unroll
    for (int w = 0; w < 4; w++) {
        const int bit = 1 << (3 - w);
        float e = 0.f;
        #pragma unroll
        for (int i = 0; i < 16; i++) {
            float p = sr[i] * sr[i] + si[i] * si[i];
            e += (i & bit) ? -p : p;
        }
        g_q[b * 4 + w] = e;
    }
}

// ============================================================================
// BACKEND: folded dconv1 + relu -> dconv2 + sigmoid.  2 images/block.
// Row stride 32 -> smem 69.6KB -> 3 CTAs/SM.
// ============================================================================
struct BackS {
    float sact[2][8][34][32];  // 69,632 B
};

__global__ __launch_bounds__(256, 3) void backend_kernel(float* __restrict__ out)
{
    extern __shared__ char raw[];
    BackS& S = *reinterpret_cast<BackS*>(raw);
    const int bid = blockIdx.x, t = threadIdx.x;
    const int b0 = 2 * bid;
    const int y = t >> 3, x0 = (t & 7) << 2;
    const int lane7 = t & 7;

    // zero only vertical padding rows (row 0 and 33 for each img/channel)
    if (t < 256) {  // 2img*8ch*2rows*8 float4 = 256
        int i = t;
        int img = i / 128, rem = i % 128;
        int ch = rem / 16, r2 = rem % 16;
        int row = (r2 < 8) ? 0 : 33, c4 = r2 % 8;
        reinterpret_cast<float4*>(&S.sact[img][ch][row][0])[c4] =
            make_float4(0.f, 0.f, 0.f, 0.f);
    }

    float qa[4], qb[4];
    #pragma unroll
    for (int k = 0; k < 4; k++) {
        qa[k] = g_q[b0 * 4 + k];
        qb[k] = g_q[(b0 + 1) * 4 + k];
    }
    __syncthreads();

    float acc[2][3][4];
    #pragma unroll
    for (int o = 0; o < 3; o++) {
        float b = c_bb[o];
        #pragma unroll
        for (int p = 0; p < 4; p++) { acc[0][o][p] = b; acc[1][o][p] = b; }
    }

    #pragma unroll 1
    for (int g = 0; g < 2; g++) {
        // ---- stage 1: folded dconv1, oc group g, both images ----
        #pragma unroll 2
        for (int o8 = 0; o8 < 8; o8++) {
            int oc = g * 8 + o8;
            int idx = (oc << 10) + (y << 5) + x0;
            float4 a0 = g_A[idx], a1 = g_A[idx + 1], a2 = g_A[idx + 2], a3 = g_A[idx + 3];
            float4 be = *reinterpret_cast<const float4*>(&g_Beff[idx]);
            {
                float v0 = fmaf(qa[0], a0.x, fmaf(qa[1], a0.y, fmaf(qa[2], a0.z, fmaf(qa[3], a0.w, be.x))));
                float v1 = fmaf(qa[0], a1.x, fmaf(qa[1], a1.y, fmaf(qa[2], a1.z, fmaf(qa[3], a1.w, be.y))));
                float v2 = fmaf(qa[0], a2.x, fmaf(qa[1], a2.y, fmaf(qa[2], a2.z, fmaf(qa[3], a2.w, be.z))));
                float v3 = fmaf(qa[0], a3.x, fmaf(qa[1], a3.y, fmaf(qa[2], a3.z, fmaf(qa[3], a3.w, be.w))));
                *reinterpret_cast<float4*>(&S.sact[0][o8][1 + y][x0]) =
                    make_float4(fmaxf(v0, 0.f), fmaxf(v1, 0.f), fmaxf(v2, 0.f), fmaxf(v3, 0.f));
            }
            {
                float v0 = fmaf(qb[0], a0.x, fmaf(qb[1], a0.y, fmaf(qb[2], a0.z, fmaf(qb[3], a0.w, be.x))));
                float v1 = fmaf(qb[0], a1.x, fmaf(qb[1], a1.y, fmaf(qb[2], a1.z, fmaf(qb[3], a1.w, be.y))));
                float v2 = fmaf(qb[0], a2.x, fmaf(qb[1], a2.y, fmaf(qb[2], a2.z, fmaf(qb[3], a2.w, be.z))));
                float v3 = fmaf(qb[0], a3.x, fmaf(qb[1], a3.y, fmaf(qb[2], a3.z, fmaf(qb[3], a3.w, be.w))));
                *reinterpret_cast<float4*>(&S.sact[1][o8][1 + y][x0]) =
                    make_float4(fmaxf(v0, 0.f), fmaxf(v1, 0.f), fmaxf(v2, 0.f), fmaxf(v3, 0.f));
            }
        }
        __syncthreads();

        // ---- stage 2: dconv2 partial, both images ----
        #pragma unroll
        for (int img = 0; img < 2; img++) {
            #pragma unroll
            for (int icg = 0; icg < 8; icg++) {
                int ic16 = g * 8 + icg;
                #pragma unroll
                for (int dy = 0; dy < 3; dy++) {
                    float v[6];
                    halo6(&S.sact[img][icg][y + dy][0], x0, lane7, v);
                    #pragma unroll
                    for (int o = 0; o < 3; o++) {
                        const float* wp = &c_wb[((o * 16 + ic16) * 3 + dy) * 3];
                        float w0 = wp[0], wA = wp[1], wB = wp[2];
                        #pragma unroll
                        for (int p = 0; p < 4; p++)
                            acc[img][o][p] = fmaf(v[p], w0,
                                fmaf(v[p + 1], wA, fmaf(v[p + 2], wB, acc[img][o][p])));
                    }
                }
            }
        }
        __syncthreads();
    }

    // ---- sigmoid epilogue, both images ----
    #pragma unroll
    for (int img = 0; img < 2; img++) {
        float* ob = out + (b0 + img) * 3072;
        #pragma unroll
        for (int o = 0; o < 3; o++) {
            float4 r = make_float4(1.f / (1.f + __expf(-acc[img][o][0])),
                                   1.f / (1.f + __expf(-acc[img][o][1])),
                                   1.f / (1.f + __expf(-acc[img][o][2])),
                                   1.f / (1.f + __expf(-acc[img][o][3])));
            *reinterpret_cast<float4*>(&ob[(o << 10) + (y << 5) + x0]) = r;
        }
    }
}

// ---------------- launch ----------------
extern "C" void kernel_launch(void* const* d_in, const int* in_sizes, int n_in,
                              void* d_out, int out_size)
{
    const float* x        = (const float*)d_in[0];
    const float* conv1_w  = (const float*)d_in[1];
    const float* conv1_b  = (const float*)d_in[2];
    const float* conv2_w  = (const float*)d_in[3];
    const float* conv2_b  = (const float*)d_in[4];
    const float* fc_w     = (const float*)d_in[5];
    const float* fc_b     = (const float*)d_in[6];
    const float* q_w      = (const float*)d_in[7];
    const float* fc2_w    = (const float*)d_in[8];
    const float* fc2_b    = (const float*)d_in[9];
    const float* dconv1_w = (const float*)d_in[10];
    const float* dconv1_b = (const float*)d_in[11];
    const float* dconv2_w = (const float*)d_in[12];
    const float* dconv2_b = (const float*)d_in[13];
    float* out = (float*)d_out;

    const int batch = in_sizes[0] / (3 * 32 * 32);

    cudaMemcpyToSymbolAsync(c_w1, conv1_w, 432 * sizeof(float), 0, cudaMemcpyDeviceToDevice);
    cudaMemcpyToSymbolAsync(c_b1, conv1_b, 16 * sizeof(float), 0, cudaMemcpyDeviceToDevice);
    cudaMemcpyToSymbolAsync(c_w2, conv2_w, 1152 * sizeof(float), 0, cudaMemcpyDeviceToDevice);
    cudaMemcpyToSymbolAsync(c_b2, conv2_b, 8 * sizeof(float), 0, cudaMemcpyDeviceToDevice);
    cudaMemcpyToSymbolAsync(c_fcb, fc_b, 4 * sizeof(float), 0, cudaMemcpyDeviceToDevice);
    cudaMemcpyToSymbolAsync(c_wb, dconv2_w, 432 * sizeof(float), 0, cudaMemcpyDeviceToDevice);
    cudaMemcpyToSymbolAsync(c_bb, dconv2_b, 3 * sizeof(float), 0, cudaMemcpyDeviceToDevice);

    cudaFuncSetAttribute(frontend_kernel, cudaFuncAttributeMaxDynamicSharedMemorySize,
                         (int)sizeof(FrontS));
    cudaFuncSetAttribute(backend_kernel, cudaFuncAttributeMaxDynamicSharedMemorySize,
                         (int)sizeof(BackS));

    prep_kernel<<<64, 256>>>(fc_w, fc2_w, fc2_b, dconv1_w, dconv1_b, q_w);
    frontend_kernel<<<batch, 256, sizeof(FrontS)>>>(x);
    quantum_kernel<<<(batch + 255) / 256, 256>>>(batch);
    backend_kernel<<<batch / 2, 256, sizeof(BackS)>>>(out);
}